// round 7
// baseline (speedup 1.0000x reference)
#include <cuda_runtime.h>
#include <math.h>

#define BB 128
#define TT 512
#define WW 64
#define DD 128
#define CC 256
#define KS 12
#define TP 500

// ---------------- device scratch (no runtime allocation allowed) ----------------
__device__ float g_z[(size_t)BB * TT * DD];        // 33.5 MB  (B,T,D) normalized z
__device__ float g_xp[(size_t)BB * TT * 3 * CC];   // 201 MB   (B,T,768) x_proj (= z@Wi + bi)
__device__ float g_c[(size_t)BB * TT * CC];        // 67 MB    (B,T,C) GRU hidden states
__device__ float g_whT[3 * CC * CC];               // Wh transposed: [col(0..767)][k(0..255)]
__device__ double g_loss;
__device__ int    g_cnt;

// ---------------- init accumulators ----------------
__global__ void k_init() { g_loss = 0.0; g_cnt = 0; }

// ---------------- transpose Wh once per launch ----------------
__global__ void k_wht(const float* __restrict__ Wh) {
    int i = blockIdx.x * 256 + threadIdx.x;       // i = col*256 + kk
    if (i < 3 * CC * CC) {
        int kk = i & 255;
        int col = i >> 8;
        g_whT[i] = Wh[(size_t)kk * 768 + col];
    }
}

// ---------------- z = l2norm(rr @ We + be) ----------------
// grid (T/64, B), block 128 (one thread per d)
__global__ __launch_bounds__(128) void k_z(const float* __restrict__ rr,
                                           const float* __restrict__ We,
                                           const float* __restrict__ be) {
    __shared__ float Wes[64 * 128];
    __shared__ float rs[64];
    __shared__ float red[4];
    int b = blockIdx.y;
    int t0 = blockIdx.x << 6;
    int tid = threadIdx.x;
    for (int i = tid; i < 64 * 128; i += 128) Wes[i] = We[i];
    float bias = be[tid];
    __syncthreads();
    for (int tt = 0; tt < 64; tt++) {
        int t = t0 + tt;
        if (tid < 64) rs[tid] = rr[((size_t)b * TT + t) * WW + tid];
        __syncthreads();
        float acc = bias;
#pragma unroll
        for (int w = 0; w < 64; w++) acc += rs[w] * Wes[w * 128 + tid];
        float ss = acc * acc;
#pragma unroll
        for (int o = 16; o; o >>= 1) ss += __shfl_xor_sync(0xffffffffu, ss, o);
        if ((tid & 31) == 0) red[tid >> 5] = ss;
        __syncthreads();
        float tot = red[0] + red[1] + red[2] + red[3];
        float scale = 1.0f / fmaxf(sqrtf(tot), 1e-12f);
        g_z[((size_t)b * TT + t) * DD + tid] = acc * scale;
        __syncthreads();
    }
}

// ---------------- x_proj = z @ Wi + bi  (M=65536, N=768, K=128) ----------------
__global__ __launch_bounds__(256) void k_xproj(const float* __restrict__ Wi,
                                               const float* __restrict__ bi) {
    __shared__ float As[32 * 132];  // [kk][r]
    __shared__ float Bs[32 * 132];  // [kk][n]
    int tid = threadIdx.x;
    int tx = tid & 15, ty = tid >> 4;
    int m0 = blockIdx.y << 7, n0 = blockIdx.x << 7;
    float acc[8][8] = {};
    for (int kc = 0; kc < DD; kc += 32) {
        for (int i = tid; i < 4096; i += 256) {
            int r = i >> 5, kk = i & 31;
            As[kk * 132 + r] = g_z[(size_t)(m0 + r) * DD + kc + kk];
        }
        for (int i = tid; i < 4096; i += 256) {
            int kk = i >> 7, n = i & 127;
            Bs[kk * 132 + n] = Wi[(size_t)(kc + kk) * 768 + n0 + n];
        }
        __syncthreads();
#pragma unroll
        for (int kk = 0; kk < 32; kk++) {
            float4 a1 = *(const float4*)&As[kk * 132 + ty * 4];
            float4 a2 = *(const float4*)&As[kk * 132 + 64 + ty * 4];
            float4 b1 = *(const float4*)&Bs[kk * 132 + tx * 4];
            float4 b2 = *(const float4*)&Bs[kk * 132 + 64 + tx * 4];
            float av[8] = {a1.x, a1.y, a1.z, a1.w, a2.x, a2.y, a2.z, a2.w};
            float bv[8] = {b1.x, b1.y, b1.z, b1.w, b2.x, b2.y, b2.z, b2.w};
#pragma unroll
            for (int i = 0; i < 8; i++)
#pragma unroll
                for (int j = 0; j < 8; j++) acc[i][j] += av[i] * bv[j];
        }
        __syncthreads();
    }
#pragma unroll
    for (int i = 0; i < 8; i++) {
        int r = m0 + ((i < 4) ? ty * 4 + i : 64 + ty * 4 + i - 4);
#pragma unroll
        for (int j = 0; j < 8; j++) {
            int c = n0 + ((j < 4) ? tx * 4 + j : 64 + tx * 4 + j - 4);
            g_xp[(size_t)r * 768 + c] = acc[i][j] + bi[c];
        }
    }
}

// ---------------- persistent GRU: all 512 steps in one kernel ----------------
// grid (8 c-chunks, 16 row-groups), cluster = 8 CTAs along x (one row-group).
// Wh held in registers for the entire kernel; per-step sync = barrier.cluster.
__global__ void __cluster_dims__(8, 1, 1) __launch_bounds__(256, 1)
k_gru_persist(const float* __restrict__ bh) {
    __shared__ float hs[8 * 256];   // h_{t-1} for this row-group (8 rows x 256 ch)
    __shared__ float gp[8 * 96];    // gate pre-activations [row][gate*32+ch]
    int tid = threadIdx.x;
    int w = tid >> 5, l = tid & 31;
    int kseg = l & 7;               // lane owns k in [kseg*32, kseg*32+32)
    int colgrp = l >> 3;            // 4 column-groups of 3 cols per warp
    int cb0 = blockIdx.x << 5;      // channel chunk base
    int rb0 = blockIdx.y << 3;      // row-group base
    int bc0 = w * 12 + colgrp * 3;  // block-col base (block cols = gate*32+ch, 0..95)

    // Load this thread's Wh slice ONCE: 3 columns x 32 k-values
    float4 Wreg[3][8];
#pragma unroll
    for (int i = 0; i < 3; i++) {
        int bc = bc0 + i;
        int gate = bc >> 5, ch = bc & 31;
        const float4* src =
            (const float4*)&g_whT[(size_t)(gate * 256 + cb0 + ch) * 256 + kseg * 32];
#pragma unroll
        for (int j = 0; j < 8; j++) Wreg[i][j] = src[j];
    }

    // Update-phase mapping: thread (ur, uc) handles row rb0+ur, channel cb0+uc
    int ur = tid >> 5, uc = tid & 31;
    int cg = cb0 + uc;
    int b = rb0 + ur;
    float bhr = bh[cg], bhz = bh[256 + cg], bhn = bh[512 + cg];
    const float* xpb = g_xp + (size_t)b * TT * 768;
    float* crow = g_c + (size_t)b * TT * CC;

    // staging indices: each thread stages 8 consecutive floats of hs
    int sflat = tid * 8;
    int sr = sflat >> 8, skk = sflat & 255;

    for (int t = 0; t < TT; t++) {
        // ---- stage h_{t-1} into smem (cross-CTA values arrive via L2, ld.cg) ----
        if (t == 0) {
            *(float4*)&hs[sflat]     = make_float4(0.f, 0.f, 0.f, 0.f);
            *(float4*)&hs[sflat + 4] = make_float4(0.f, 0.f, 0.f, 0.f);
        } else {
            const float4* s =
                (const float4*)&g_c[((size_t)(rb0 + sr) * TT + (t - 1)) * CC + skk];
            *(float4*)&hs[sflat]     = __ldcg(s);
            *(float4*)&hs[sflat + 4] = __ldcg(s + 1);
        }
        // prefetch x_proj for the update phase (consumed after compute)
        float xr = __ldg(&xpb[(size_t)t * 768 + cg]);
        float xz = __ldg(&xpb[(size_t)t * 768 + 256 + cg]);
        float xn = __ldg(&xpb[(size_t)t * 768 + 512 + cg]);
        __syncthreads();

        // ---- h @ Wh: k split over 8-lane groups, reduce with 3-level butterfly ----
#pragma unroll
        for (int r = 0; r < 8; r++) {
            const float4* hrow = (const float4*)&hs[r * 256 + kseg * 32];
            float4 hv[8];
#pragma unroll
            for (int j = 0; j < 8; j++) {           // kseg-rotated order: bank-conflict-free
                int jj = (j + kseg) & 7;
                hv[jj] = hrow[jj];
            }
            float p0 = 0.f, p1 = 0.f, p2 = 0.f;
#pragma unroll
            for (int j = 0; j < 8; j++) {
                float4 h4 = hv[j];
                float4 w0 = Wreg[0][j], w1 = Wreg[1][j], w2 = Wreg[2][j];
                p0 += h4.x * w0.x + h4.y * w0.y + h4.z * w0.z + h4.w * w0.w;
                p1 += h4.x * w1.x + h4.y * w1.y + h4.z * w1.z + h4.w * w1.w;
                p2 += h4.x * w2.x + h4.y * w2.y + h4.z * w2.z + h4.w * w2.w;
            }
#pragma unroll
            for (int off = 4; off; off >>= 1) {
                p0 += __shfl_xor_sync(0xffffffffu, p0, off);
                p1 += __shfl_xor_sync(0xffffffffu, p1, off);
                p2 += __shfl_xor_sync(0xffffffffu, p2, off);
            }
            if (kseg < 3)
                gp[r * 96 + bc0 + kseg] = (kseg == 0) ? p0 : ((kseg == 1) ? p1 : p2);
        }
        __syncthreads();

        // ---- gates + state update ----
        {
            float hr = gp[ur * 96 + uc]      + bhr;
            float hz = gp[ur * 96 + 32 + uc] + bhz;
            float hn = gp[ur * 96 + 64 + uc] + bhn;
            float rg = 1.f / (1.f + expf(-(xr + hr)));
            float zg = 1.f / (1.f + expf(-(xz + hz)));
            float ng = tanhf(xn + rg * hn);
            float hp = hs[ur * 256 + cg];
            crow[(size_t)t * CC + cg] = (1.f - zg) * ng + zg * hp;
        }

        // ---- cluster barrier: release h_t to the 7 peer CTAs of this row-group ----
        asm volatile("barrier.cluster.arrive.aligned;" ::: "memory");
        asm volatile("barrier.cluster.wait.aligned;" ::: "memory");
    }
}

// ---------------- fused pred GEMM + norm + logits + LSE/argmax per (k,t) ----------------
// grid (500, 12), block 256
#define LOSS_SMEM ((2 * 128 * 132 + 128 + 16) * 4)
__global__ __launch_bounds__(256) void k_loss(const float* __restrict__ Wkw,
                                              const float* __restrict__ Wkb) {
    extern __shared__ float sm[];
    float* Psm = sm;                  // 128x132: raw pred, later logits
    float* Zsm = sm + 128 * 132;      // 128x132: zf tile (aliases As/Bs)
    float* As = Zsm;                  // 32x132  (stage1, [kk][r])
    float* Bs = Zsm + 32 * 132;       // 32x132  (stage1, [kk][d])
    float* rnorm = sm + 2 * 128 * 132;
    float* red = rnorm + 128;

    int t = blockIdx.x, k = blockIdx.y;
    int tid = threadIdx.x;
    int tx = tid & 15, ty = tid >> 4;
    int rows[8], cols[8];
#pragma unroll
    for (int i = 0; i < 8; i++) {
        rows[i] = (i < 4) ? ty * 4 + i : 64 + ty * 4 + i - 4;
        cols[i] = (i < 4) ? tx * 4 + i : 64 + tx * 4 + i - 4;
    }

    // stage 1: P = c_t @ Wk[k]  (128x128, K=256)
    float acc[8][8] = {};
    for (int kc = 0; kc < CC; kc += 32) {
        for (int i = tid; i < 4096; i += 256) {
            int r = i >> 5, kk = i & 31;
            As[kk * 132 + r] = g_c[((size_t)r * TT + t) * CC + kc + kk];
        }
        for (int i = tid; i < 4096; i += 256) {
            int kk = i >> 7, d = i & 127;
            Bs[kk * 132 + d] = Wkw[((size_t)k * CC + kc + kk) * DD + d];
        }
        __syncthreads();
#pragma unroll
        for (int kk = 0; kk < 32; kk++) {
            float4 a1 = *(const float4*)&As[kk * 132 + ty * 4];
            float4 a2 = *(const float4*)&As[kk * 132 + 64 + ty * 4];
            float4 b1 = *(const float4*)&Bs[kk * 132 + tx * 4];
            float4 b2 = *(const float4*)&Bs[kk * 132 + 64 + tx * 4];
            float av[8] = {a1.x, a1.y, a1.z, a1.w, a2.x, a2.y, a2.z, a2.w};
            float bv[8] = {b1.x, b1.y, b1.z, b1.w, b2.x, b2.y, b2.z, b2.w};
#pragma unroll
            for (int i = 0; i < 8; i++)
#pragma unroll
                for (int j = 0; j < 8; j++) acc[i][j] += av[i] * bv[j];
        }
        __syncthreads();
    }
    // bias + stash raw pred
#pragma unroll
    for (int i = 0; i < 8; i++)
#pragma unroll
        for (int j = 0; j < 8; j++)
            Psm[rows[i] * 132 + cols[j]] = acc[i][j] + Wkb[k * DD + cols[j]];
    __syncthreads();

    // per-row 1/||P||  (normalization commutes with the dot product)
    if (tid < 128) {
        const float4* p = (const float4*)&Psm[tid * 132];
        float ss = 0.f;
#pragma unroll
        for (int q = 0; q < 32; q++) {
            float4 v = p[q];
            ss += v.x * v.x + v.y * v.y + v.z * v.z + v.w * v.w;
        }
        rnorm[tid] = 1.f / fmaxf(sqrtf(ss), 1e-12f);
    }
    // load zf tile: Z[c][d] = z[c, t+k+1, d]
    for (int i = tid; i < 16384; i += 256) {
        int cidx = i >> 7, d = i & 127;
        Zsm[cidx * 132 + d] = g_z[((size_t)cidx * TT + t + k + 1) * DD + d];
    }
    __syncthreads();

    // stage 2: S = P @ Z^T  (128x128, K=128)
    float acc2[8][8] = {};
#pragma unroll 2
    for (int d = 0; d < 128; d += 4) {
        float4 pv[8], zv[8];
#pragma unroll
        for (int i = 0; i < 8; i++) pv[i] = *(const float4*)&Psm[rows[i] * 132 + d];
#pragma unroll
        for (int j = 0; j < 8; j++) zv[j] = *(const float4*)&Zsm[cols[j] * 132 + d];
#pragma unroll
        for (int i = 0; i < 8; i++)
#pragma unroll
            for (int j = 0; j < 8; j++)
                acc2[i][j] += pv[i].x * zv[j].x + pv[i].y * zv[j].y +
                              pv[i].z * zv[j].z + pv[i].w * zv[j].w;
    }
    __syncthreads();  // done reading raw P
    // logits = rnorm[b] * S / TEMP  (TEMP = 0.1)
#pragma unroll
    for (int i = 0; i < 8; i++) {
        float rn = rnorm[rows[i]] * 10.0f;
#pragma unroll
        for (int j = 0; j < 8; j++)
            Psm[rows[i] * 132 + cols[j]] = acc2[i][j] * rn;
    }
    __syncthreads();

    // per-row LSE, diag, argmax
    float lossv = 0.f;
    int corr = 0;
    if (tid < 128) {
        const float* L = &Psm[tid * 132];
        float m = -1e30f;
        int am = 0;
        for (int cc = 0; cc < 128; cc++) {
            float v = L[cc];
            if (v > m) { m = v; am = cc; }
        }
        float s = 0.f;
        for (int cc = 0; cc < 128; cc++) s += expf(L[cc] - m);
        lossv = m + logf(s) - L[tid];
        corr = (am == tid) ? 1 : 0;
    }
#pragma unroll
    for (int o = 16; o; o >>= 1) {
        lossv += __shfl_xor_sync(0xffffffffu, lossv, o);
        corr += __shfl_xor_sync(0xffffffffu, corr, o);
    }
    int wid = tid >> 5;
    if ((tid & 31) == 0) {
        red[wid] = lossv;
        ((int*)red)[8 + wid] = corr;
    }
    __syncthreads();
    if (tid == 0) {
        float s = 0.f;
        int ct = 0;
        for (int w = 0; w < 8; w++) { s += red[w]; ct += ((int*)red)[8 + w]; }
        atomicAdd(&g_loss, (double)s);
        atomicAdd(&g_cnt, ct);
    }
}

// ---------------- finalize scalars ----------------
__global__ void k_fin(float* out) {
    const double n = (double)KS * TP * BB;
    out[0] = (float)(g_loss / n);
    out[1] = (float)(100.0 * (double)g_cnt / n);
}

// ---------------- copy z_seq, c_seq into d_out ----------------
__global__ void k_copy(float* out, long long out_size) {
    size_t i0 = (size_t)blockIdx.x * blockDim.x + threadIdx.x;
    size_t stride = (size_t)gridDim.x * blockDim.x;
    const size_t NZ = (size_t)BB * TT * DD;
    const size_t NC = (size_t)BB * TT * CC;
    size_t avail = (out_size > 2) ? (size_t)(out_size - 2) : 0;
    size_t nz = NZ < avail ? NZ : avail;
    size_t nc2 = (avail > NZ) ? ((NC < avail - NZ) ? NC : avail - NZ) : 0;
    float2* oz = (float2*)(out + 2);
    const float2* z2 = (const float2*)g_z;
    for (size_t i = i0; i < nz / 2; i += stride) oz[i] = z2[i];
    float2* oc = (float2*)(out + 2 + NZ);
    const float2* c2 = (const float2*)g_c;
    for (size_t i = i0; i < nc2 / 2; i += stride) oc[i] = c2[i];
}

extern "C" void kernel_launch(void* const* d_in, const int* in_sizes, int n_in,
                              void* d_out, int out_size) {
    const float* rr  = (const float*)d_in[0];
    const float* We  = (const float*)d_in[1];
    const float* be  = (const float*)d_in[2];
    const float* Wi  = (const float*)d_in[3];
    const float* Wh  = (const float*)d_in[4];
    const float* bi  = (const float*)d_in[5];
    const float* bh  = (const float*)d_in[6];
    const float* Wkw = (const float*)d_in[7];
    const float* Wkb = (const float*)d_in[8];
    float* out = (float*)d_out;

    cudaFuncSetAttribute(k_loss, cudaFuncAttributeMaxDynamicSharedMemorySize, LOSS_SMEM);

    k_init<<<1, 1>>>();
    k_z<<<dim3(TT / 64, BB), 128>>>(rr, We, be);
    k_wht<<<(3 * CC * CC + 255) / 256, 256>>>(Wh);
    k_xproj<<<dim3(6, (BB * TT) / 128), 256>>>(Wi, bi);
    k_gru_persist<<<dim3(8, 16), 256>>>(bh);
    k_loss<<<dim3(TP, KS), 256, LOSS_SMEM>>>(Wkw, Wkb);
    k_fin<<<1, 1>>>(out);
    k_copy<<<2048, 256>>>(out, (long long)out_size);
}

// round 8
// speedup vs baseline: 7.2450x; 7.2450x over previous
#include <cuda_runtime.h>
#include <math.h>

#define BB 128
#define TT 512
#define WW 64
#define DD 128
#define CC 256
#define KS 12
#define TP 500

// ---------------- device scratch (no runtime allocation allowed) ----------------
__device__ float g_z[(size_t)BB * TT * DD];        // 33.5 MB  (B,T,D) normalized z
__device__ float g_xp[(size_t)BB * TT * 3 * CC];   // 201 MB   (B,T,768) x_proj (= z@Wi + bi)
__device__ float g_c[(size_t)BB * TT * CC];        // 67 MB    (B,T,C) GRU hidden states
__device__ float g_whT[3 * CC * CC];               // Wh transposed: [col(0..767)][k(0..255)]
__device__ double g_loss;
__device__ int    g_cnt;
__device__ unsigned g_sync[16];                    // per-rowgroup step counters

// ---------------- init accumulators ----------------
__global__ void k_init() {
    g_loss = 0.0; g_cnt = 0;
    for (int i = 0; i < 16; i++) g_sync[i] = 0u;
}

// ---------------- transpose Wh once per launch ----------------
__global__ void k_wht(const float* __restrict__ Wh) {
    int i = blockIdx.x * 256 + threadIdx.x;       // i = col*256 + kk
    if (i < 3 * CC * CC) {
        int kk = i & 255;
        int col = i >> 8;
        g_whT[i] = Wh[(size_t)kk * 768 + col];
    }
}

// ---------------- z = l2norm(rr @ We + be) ----------------
// grid (T/64, B), block 128 (one thread per d)
__global__ __launch_bounds__(128) void k_z(const float* __restrict__ rr,
                                           const float* __restrict__ We,
                                           const float* __restrict__ be) {
    __shared__ float Wes[64 * 128];
    __shared__ float rs[64];
    __shared__ float red[4];
    int b = blockIdx.y;
    int t0 = blockIdx.x << 6;
    int tid = threadIdx.x;
    for (int i = tid; i < 64 * 128; i += 128) Wes[i] = We[i];
    float bias = be[tid];
    __syncthreads();
    for (int tt = 0; tt < 64; tt++) {
        int t = t0 + tt;
        if (tid < 64) rs[tid] = rr[((size_t)b * TT + t) * WW + tid];
        __syncthreads();
        float acc = bias;
#pragma unroll
        for (int w = 0; w < 64; w++) acc += rs[w] * Wes[w * 128 + tid];
        float ss = acc * acc;
#pragma unroll
        for (int o = 16; o; o >>= 1) ss += __shfl_xor_sync(0xffffffffu, ss, o);
        if ((tid & 31) == 0) red[tid >> 5] = ss;
        __syncthreads();
        float tot = red[0] + red[1] + red[2] + red[3];
        float scale = 1.0f / fmaxf(sqrtf(tot), 1e-12f);
        g_z[((size_t)b * TT + t) * DD + tid] = acc * scale;
        __syncthreads();
    }
}

// ---------------- x_proj = z @ Wi + bi  (M=65536, N=768, K=128) ----------------
__global__ __launch_bounds__(256) void k_xproj(const float* __restrict__ Wi,
                                               const float* __restrict__ bi) {
    __shared__ float As[32 * 132];  // [kk][r]
    __shared__ float Bs[32 * 132];  // [kk][n]
    int tid = threadIdx.x;
    int tx = tid & 15, ty = tid >> 4;
    int m0 = blockIdx.y << 7, n0 = blockIdx.x << 7;
    float acc[8][8] = {};
    for (int kc = 0; kc < DD; kc += 32) {
        for (int i = tid; i < 4096; i += 256) {
            int r = i >> 5, kk = i & 31;
            As[kk * 132 + r] = g_z[(size_t)(m0 + r) * DD + kc + kk];
        }
        for (int i = tid; i < 4096; i += 256) {
            int kk = i >> 7, n = i & 127;
            Bs[kk * 132 + n] = Wi[(size_t)(kc + kk) * 768 + n0 + n];
        }
        __syncthreads();
#pragma unroll
        for (int kk = 0; kk < 32; kk++) {
            float4 a1 = *(const float4*)&As[kk * 132 + ty * 4];
            float4 a2 = *(const float4*)&As[kk * 132 + 64 + ty * 4];
            float4 b1 = *(const float4*)&Bs[kk * 132 + tx * 4];
            float4 b2 = *(const float4*)&Bs[kk * 132 + 64 + tx * 4];
            float av[8] = {a1.x, a1.y, a1.z, a1.w, a2.x, a2.y, a2.z, a2.w};
            float bv[8] = {b1.x, b1.y, b1.z, b1.w, b2.x, b2.y, b2.z, b2.w};
#pragma unroll
            for (int i = 0; i < 8; i++)
#pragma unroll
                for (int j = 0; j < 8; j++) acc[i][j] += av[i] * bv[j];
        }
        __syncthreads();
    }
#pragma unroll
    for (int i = 0; i < 8; i++) {
        int r = m0 + ((i < 4) ? ty * 4 + i : 64 + ty * 4 + i - 4);
#pragma unroll
        for (int j = 0; j < 8; j++) {
            int c = n0 + ((j < 4) ? tx * 4 + j : 64 + tx * 4 + j - 4);
            g_xp[(size_t)r * 768 + c] = acc[i][j] + bi[c];
        }
    }
}

// ---------------- persistent GRU: all 512 steps, atomic-flag sync ----------------
// grid (8 col-groups, 16 row-groups) = 128 CTAs <= 148 SMs -> wave-1 co-resident.
// Wh slice lives in smem for the entire kernel. Sync only among the 8 CTAs of a
// row-group via a monotone counter in L2 (release = threadfence+atomicAdd,
// acquire = leader ld.acquire.gpu spin + __syncthreads fan-out).
#define GRU2_SMEM ((96 * 260 + 8 * 256 + 8 * 3 * 256) * 4)
__global__ __launch_bounds__(256, 1) void k_gru2(const float* __restrict__ bh) {
    extern __shared__ float sm[];
    float* ws   = sm;                          // [96][260]  Wh slice (bc = gate*32+ch)
    float* hs   = sm + 96 * 260;               // [8][256]   h_{t-1}
    float* part = sm + 96 * 260 + 8 * 256;     // [8][3][256] k-octant partials

    int tid = threadIdx.x;
    int cgx = blockIdx.x;                      // col-group 0..7 (channels cb0..cb0+31)
    int rg  = blockIdx.y;                      // row-group 0..15
    int cb0 = cgx << 5;
    int rb0 = rg << 3;

    // ---- load Wh slice once (3 gates x 32 channels x 256 k) ----
    for (int i = tid; i < 96 * 64; i += 256) {           // i = bc*64 + q (float4)
        int bc = i >> 6, q = i & 63;
        int gate = bc >> 5, ch = bc & 31;
        float4 v = *(const float4*)&g_whT[(size_t)(gate * 256 + cb0 + ch) * 256 + q * 4];
        *(float4*)&ws[bc * 260 + q * 4] = v;
    }

    int uc = tid & 31;                 // channel within chunk
    int kh = tid >> 5;                 // k-octant (k in [kh*32, kh*32+32))
    int cg = cb0 + uc;
    float bhr = bh[cg], bhz = bh[256 + cg], bhn = bh[512 + cg];

    int ur = kh;                       // update-phase row = warp id
    int b  = rb0 + ur;
    const float* xpb = g_xp + (size_t)b * TT * 768;
    float* crow = g_c + (size_t)b * TT * CC;

    // staging: each thread stages 8 consecutive floats of hs
    int sflat = tid * 8;
    int sr = sflat >> 8, skk = sflat & 255;

    const float* wr = &ws[(0  + uc) * 260 + kh * 32];
    const float* wz = &ws[(32 + uc) * 260 + kh * 32];
    const float* wn = &ws[(64 + uc) * 260 + kh * 32];

    for (int t = 0; t < TT; t++) {
        // ---- stage h_{t-1} (peer slices arrive via L2) ----
        if (t == 0) {
            *(float4*)&hs[sflat]     = make_float4(0.f, 0.f, 0.f, 0.f);
            *(float4*)&hs[sflat + 4] = make_float4(0.f, 0.f, 0.f, 0.f);
        } else {
            const float4* s =
                (const float4*)&g_c[((size_t)(rb0 + sr) * TT + (t - 1)) * CC + skk];
            *(float4*)&hs[sflat]     = __ldcg(s);
            *(float4*)&hs[sflat + 4] = __ldcg(s + 1);
        }
        // prefetch x_proj (consumed in update phase; DRAM latency hidden by compute)
        float xr = __ldg(&xpb[(size_t)t * 768 + cg]);
        float xz = __ldg(&xpb[(size_t)t * 768 + 256 + cg]);
        float xn = __ldg(&xpb[(size_t)t * 768 + 512 + cg]);
        __syncthreads();

        // ---- h @ Wh over this thread's k-octant, all 8 rows, 3 gates ----
        float a0[8] = {}, a1[8] = {}, a2[8] = {};
#pragma unroll
        for (int j = 0; j < 8; j++) {
            float4 w0 = *(const float4*)&wr[j * 4];
            float4 w1 = *(const float4*)&wz[j * 4];
            float4 w2 = *(const float4*)&wn[j * 4];
#pragma unroll
            for (int r = 0; r < 8; r++) {
                float4 h4 = *(const float4*)&hs[r * 256 + kh * 32 + j * 4];
                a0[r] += h4.x * w0.x + h4.y * w0.y + h4.z * w0.z + h4.w * w0.w;
                a1[r] += h4.x * w1.x + h4.y * w1.y + h4.z * w1.z + h4.w * w1.w;
                a2[r] += h4.x * w2.x + h4.y * w2.y + h4.z * w2.z + h4.w * w2.w;
            }
        }
        // ---- cross-octant partials ----
#pragma unroll
        for (int r = 0; r < 8; r++) {
            part[(r * 3 + 0) * 256 + kh * 32 + uc] = a0[r];
            part[(r * 3 + 1) * 256 + kh * 32 + uc] = a1[r];
            part[(r * 3 + 2) * 256 + kh * 32 + uc] = a2[r];
        }
        __syncthreads();

        // ---- reduce + gates + state update: thread (ur, uc) ----
        {
            float hr = bhr, hz = bhz, hn = bhn;
#pragma unroll
            for (int q = 0; q < 8; q++) {
                hr += part[(ur * 3 + 0) * 256 + q * 32 + uc];
                hz += part[(ur * 3 + 1) * 256 + q * 32 + uc];
                hn += part[(ur * 3 + 2) * 256 + q * 32 + uc];
            }
            float rgt = 1.f / (1.f + expf(-(xr + hr)));
            float zgt = 1.f / (1.f + expf(-(xz + hz)));
            float ngt = tanhf(xn + rgt * hn);
            float hp = hs[ur * 256 + cg];
            crow[(size_t)t * CC + cg] = (1.f - zgt) * ngt + zgt * hp;
        }

        // ---- release h_t to the 7 peer CTAs, then acquire theirs ----
        __threadfence();
        __syncthreads();
        if (tid == 0) {
            atomicAdd(&g_sync[rg], 1u);
            unsigned target = 8u * (unsigned)(t + 1);
            unsigned v;
            do {
                asm volatile("ld.acquire.gpu.u32 %0, [%1];"
                             : "=r"(v) : "l"(&g_sync[rg]) : "memory");
            } while (v < target);
        }
        __syncthreads();
    }
}

// ---------------- fused pred GEMM + norm + logits + LSE/argmax per (k,t) ----------------
// grid (500, 12), block 256
#define LOSS_SMEM ((2 * 128 * 132 + 128 + 16) * 4)
__global__ __launch_bounds__(256) void k_loss(const float* __restrict__ Wkw,
                                              const float* __restrict__ Wkb) {
    extern __shared__ float sm[];
    float* Psm = sm;                  // 128x132: raw pred, later logits
    float* Zsm = sm + 128 * 132;      // 128x132: zf tile (aliases As/Bs)
    float* As = Zsm;                  // 32x132  (stage1, [kk][r])
    float* Bs = Zsm + 32 * 132;       // 32x132  (stage1, [kk][d])
    float* rnorm = sm + 2 * 128 * 132;
    float* red = rnorm + 128;

    int t = blockIdx.x, k = blockIdx.y;
    int tid = threadIdx.x;
    int tx = tid & 15, ty = tid >> 4;
    int rows[8], cols[8];
#pragma unroll
    for (int i = 0; i < 8; i++) {
        rows[i] = (i < 4) ? ty * 4 + i : 64 + ty * 4 + i - 4;
        cols[i] = (i < 4) ? tx * 4 + i : 64 + tx * 4 + i - 4;
    }

    // stage 1: P = c_t @ Wk[k]  (128x128, K=256)
    float acc[8][8] = {};
    for (int kc = 0; kc < CC; kc += 32) {
        for (int i = tid; i < 4096; i += 256) {
            int r = i >> 5, kk = i & 31;
            As[kk * 132 + r] = g_c[((size_t)r * TT + t) * CC + kc + kk];
        }
        for (int i = tid; i < 4096; i += 256) {
            int kk = i >> 7, d = i & 127;
            Bs[kk * 132 + d] = Wkw[((size_t)k * CC + kc + kk) * DD + d];
        }
        __syncthreads();
#pragma unroll
        for (int kk = 0; kk < 32; kk++) {
            float4 a1 = *(const float4*)&As[kk * 132 + ty * 4];
            float4 a2 = *(const float4*)&As[kk * 132 + 64 + ty * 4];
            float4 b1 = *(const float4*)&Bs[kk * 132 + tx * 4];
            float4 b2 = *(const float4*)&Bs[kk * 132 + 64 + tx * 4];
            float av[8] = {a1.x, a1.y, a1.z, a1.w, a2.x, a2.y, a2.z, a2.w};
            float bv[8] = {b1.x, b1.y, b1.z, b1.w, b2.x, b2.y, b2.z, b2.w};
#pragma unroll
            for (int i = 0; i < 8; i++)
#pragma unroll
                for (int j = 0; j < 8; j++) acc[i][j] += av[i] * bv[j];
        }
        __syncthreads();
    }
    // bias + stash raw pred
#pragma unroll
    for (int i = 0; i < 8; i++)
#pragma unroll
        for (int j = 0; j < 8; j++)
            Psm[rows[i] * 132 + cols[j]] = acc[i][j] + Wkb[k * DD + cols[j]];
    __syncthreads();

    // per-row 1/||P||  (normalization commutes with the dot product)
    if (tid < 128) {
        const float4* p = (const float4*)&Psm[tid * 132];
        float ss = 0.f;
#pragma unroll
        for (int q = 0; q < 32; q++) {
            float4 v = p[q];
            ss += v.x * v.x + v.y * v.y + v.z * v.z + v.w * v.w;
        }
        rnorm[tid] = 1.f / fmaxf(sqrtf(ss), 1e-12f);
    }
    // load zf tile: Z[c][d] = z[c, t+k+1, d]
    for (int i = tid; i < 16384; i += 256) {
        int cidx = i >> 7, d = i & 127;
        Zsm[cidx * 132 + d] = g_z[((size_t)cidx * TT + t + k + 1) * DD + d];
    }
    __syncthreads();

    // stage 2: S = P @ Z^T  (128x128, K=128)
    float acc2[8][8] = {};
#pragma unroll 2
    for (int d = 0; d < 128; d += 4) {
        float4 pv[8], zv[8];
#pragma unroll
        for (int i = 0; i < 8; i++) pv[i] = *(const float4*)&Psm[rows[i] * 132 + d];
#pragma unroll
        for (int j = 0; j < 8; j++) zv[j] = *(const float4*)&Zsm[cols[j] * 132 + d];
#pragma unroll
        for (int i = 0; i < 8; i++)
#pragma unroll
            for (int j = 0; j < 8; j++)
                acc2[i][j] += pv[i].x * zv[j].x + pv[i].y * zv[j].y +
                              pv[i].z * zv[j].z + pv[i].w * zv[j].w;
    }
    __syncthreads();  // done reading raw P
    // logits = rnorm[b] * S / TEMP  (TEMP = 0.1)
#pragma unroll
    for (int i = 0; i < 8; i++) {
        float rn = rnorm[rows[i]] * 10.0f;
#pragma unroll
        for (int j = 0; j < 8; j++)
            Psm[rows[i] * 132 + cols[j]] = acc2[i][j] * rn;
    }
    __syncthreads();

    // per-row LSE, diag, argmax
    float lossv = 0.f;
    int corr = 0;
    if (tid < 128) {
        const float* L = &Psm[tid * 132];
        float m = -1e30f;
        int am = 0;
        for (int cc = 0; cc < 128; cc++) {
            float v = L[cc];
            if (v > m) { m = v; am = cc; }
        }
        float s = 0.f;
        for (int cc = 0; cc < 128; cc++) s += expf(L[cc] - m);
        lossv = m + logf(s) - L[tid];
        corr = (am == tid) ? 1 : 0;
    }
#pragma unroll
    for (int o = 16; o; o >>= 1) {
        lossv += __shfl_xor_sync(0xffffffffu, lossv, o);
        corr += __shfl_xor_sync(0xffffffffu, corr, o);
    }
    int wid = tid >> 5;
    if ((tid & 31) == 0) {
        red[wid] = lossv;
        ((int*)red)[8 + wid] = corr;
    }
    __syncthreads();
    if (tid == 0) {
        float s = 0.f;
        int ct = 0;
        for (int w = 0; w < 8; w++) { s += red[w]; ct += ((int*)red)[8 + w]; }
        atomicAdd(&g_loss, (double)s);
        atomicAdd(&g_cnt, ct);
    }
}

// ---------------- finalize scalars ----------------
__global__ void k_fin(float* out) {
    const double n = (double)KS * TP * BB;
    out[0] = (float)(g_loss / n);
    out[1] = (float)(100.0 * (double)g_cnt / n);
}

// ---------------- copy z_seq, c_seq into d_out ----------------
__global__ void k_copy(float* out, long long out_size) {
    size_t i0 = (size_t)blockIdx.x * blockDim.x + threadIdx.x;
    size_t stride = (size_t)gridDim.x * blockDim.x;
    const size_t NZ = (size_t)BB * TT * DD;
    const size_t NC = (size_t)BB * TT * CC;
    size_t avail = (out_size > 2) ? (size_t)(out_size - 2) : 0;
    size_t nz = NZ < avail ? NZ : avail;
    size_t nc2 = (avail > NZ) ? ((NC < avail - NZ) ? NC : avail - NZ) : 0;
    float2* oz = (float2*)(out + 2);
    const float2* z2 = (const float2*)g_z;
    for (size_t i = i0; i < nz / 2; i += stride) oz[i] = z2[i];
    float2* oc = (float2*)(out + 2 + NZ);
    const float2* c2 = (const float2*)g_c;
    for (size_t i = i0; i < nc2 / 2; i += stride) oc[i] = c2[i];
}

extern "C" void kernel_launch(void* const* d_in, const int* in_sizes, int n_in,
                              void* d_out, int out_size) {
    const float* rr  = (const float*)d_in[0];
    const float* We  = (const float*)d_in[1];
    const float* be  = (const float*)d_in[2];
    const float* Wi  = (const float*)d_in[3];
    const float* Wh  = (const float*)d_in[4];
    const float* bi  = (const float*)d_in[5];
    const float* bh  = (const float*)d_in[6];
    const float* Wkw = (const float*)d_in[7];
    const float* Wkb = (const float*)d_in[8];
    float* out = (float*)d_out;

    cudaFuncSetAttribute(k_gru2, cudaFuncAttributeMaxDynamicSharedMemorySize, GRU2_SMEM);
    cudaFuncSetAttribute(k_loss, cudaFuncAttributeMaxDynamicSharedMemorySize, LOSS_SMEM);

    k_init<<<1, 1>>>();
    k_z<<<dim3(TT / 64, BB), 128>>>(rr, We, be);
    k_wht<<<(3 * CC * CC + 255) / 256, 256>>>(Wh);
    k_xproj<<<dim3(6, (BB * TT) / 128), 256>>>(Wi, bi);
    k_gru2<<<dim3(8, 16), 256, GRU2_SMEM>>>(bh);
    k_loss<<<dim3(TP, KS), 256, LOSS_SMEM>>>(Wkw, Wkb);
    k_fin<<<1, 1>>>(out);
    k_copy<<<2048, 256>>>(out, (long long)out_size);
}

// round 9
// speedup vs baseline: 9.6212x; 1.3280x over previous
#include <cuda_runtime.h>
#include <math.h>

#define BB 128
#define TT 512
#define WW 64
#define DD 128
#define CC 256
#define KS 12
#define TP 500

typedef unsigned long long ull;
typedef unsigned int uint;

// ---------------- device scratch (no runtime allocation allowed) ----------------
__device__ float g_z[(size_t)BB * TT * DD];        // 33.5 MB  (B,T,D) normalized z
__device__ float g_xp[(size_t)BB * TT * 3 * CC];   // 201 MB   (B,T,768) x_proj
__device__ float g_c[(size_t)BB * TT * CC];        // 67 MB    (B,T,C) GRU hidden states
__device__ float g_whT[3 * CC * CC];               // Wh transposed: [col][k]
__device__ double g_loss;
__device__ int    g_cnt;
__device__ unsigned g_sync[16];                    // per-rowgroup step counters

__device__ __forceinline__ uint f2tf(float f) {
    uint u;
    asm("cvt.rna.tf32.f32 %0, %1;" : "=r"(u) : "f"(f));
    return u;
}
__device__ __forceinline__ ull ffma2(ull a, ull b, ull c) {
    ull d;
    asm("fma.rn.f32x2 %0, %1, %2, %3;" : "=l"(d) : "l"(a), "l"(b), "l"(c));
    return d;
}
__device__ __forceinline__ float pairsum(ull v) {
    float lo, hi;
    asm("mov.b64 {%0, %1}, %2;" : "=f"(lo), "=f"(hi) : "l"(v));
    return lo + hi;
}
#define MMA_TF32(d, a, b) \
    asm volatile("mma.sync.aligned.m16n8k8.row.col.f32.tf32.tf32.f32 " \
                 "{%0,%1,%2,%3},{%4,%5,%6,%7},{%8,%9},{%0,%1,%2,%3};" \
                 : "+f"((d)[0]), "+f"((d)[1]), "+f"((d)[2]), "+f"((d)[3]) \
                 : "r"((a)[0]), "r"((a)[1]), "r"((a)[2]), "r"((a)[3]), \
                   "r"((b)[0]), "r"((b)[1]))

// ---------------- init accumulators ----------------
__global__ void k_init() {
    g_loss = 0.0; g_cnt = 0;
    for (int i = 0; i < 16; i++) g_sync[i] = 0u;
}

// ---------------- transpose Wh once per launch ----------------
__global__ void k_wht(const float* __restrict__ Wh) {
    int i = blockIdx.x * 256 + threadIdx.x;
    if (i < 3 * CC * CC) {
        int kk = i & 255;
        int col = i >> 8;
        g_whT[i] = Wh[(size_t)kk * 768 + col];
    }
}

// ---------------- z = l2norm(rr @ We + be) ----------------
__global__ __launch_bounds__(128) void k_z(const float* __restrict__ rr,
                                           const float* __restrict__ We,
                                           const float* __restrict__ be) {
    __shared__ float Wes[64 * 128];
    __shared__ float rs[64];
    __shared__ float red[4];
    int b = blockIdx.y;
    int t0 = blockIdx.x << 6;
    int tid = threadIdx.x;
    for (int i = tid; i < 64 * 128; i += 128) Wes[i] = We[i];
    float bias = be[tid];
    __syncthreads();
    for (int tt = 0; tt < 64; tt++) {
        int t = t0 + tt;
        if (tid < 64) rs[tid] = rr[((size_t)b * TT + t) * WW + tid];
        __syncthreads();
        float acc = bias;
#pragma unroll
        for (int w = 0; w < 64; w++) acc += rs[w] * Wes[w * 128 + tid];
        float ss = acc * acc;
#pragma unroll
        for (int o = 16; o; o >>= 1) ss += __shfl_xor_sync(0xffffffffu, ss, o);
        if ((tid & 31) == 0) red[tid >> 5] = ss;
        __syncthreads();
        float tot = red[0] + red[1] + red[2] + red[3];
        float scale = 1.0f / fmaxf(sqrtf(tot), 1e-12f);
        g_z[((size_t)b * TT + t) * DD + tid] = acc * scale;
        __syncthreads();
    }
}

// ---------------- x_proj = z @ Wi + bi  (M=65536, N=768, K=128) ----------------
__global__ __launch_bounds__(256) void k_xproj(const float* __restrict__ Wi,
                                               const float* __restrict__ bi) {
    __shared__ float As[32 * 132];
    __shared__ float Bs[32 * 132];
    int tid = threadIdx.x;
    int tx = tid & 15, ty = tid >> 4;
    int m0 = blockIdx.y << 7, n0 = blockIdx.x << 7;
    float acc[8][8] = {};
    for (int kc = 0; kc < DD; kc += 32) {
        for (int i = tid; i < 4096; i += 256) {
            int r = i >> 5, kk = i & 31;
            As[kk * 132 + r] = g_z[(size_t)(m0 + r) * DD + kc + kk];
        }
        for (int i = tid; i < 4096; i += 256) {
            int kk = i >> 7, n = i & 127;
            Bs[kk * 132 + n] = Wi[(size_t)(kc + kk) * 768 + n0 + n];
        }
        __syncthreads();
#pragma unroll
        for (int kk = 0; kk < 32; kk++) {
            float4 a1 = *(const float4*)&As[kk * 132 + ty * 4];
            float4 a2 = *(const float4*)&As[kk * 132 + 64 + ty * 4];
            float4 b1 = *(const float4*)&Bs[kk * 132 + tx * 4];
            float4 b2 = *(const float4*)&Bs[kk * 132 + 64 + tx * 4];
            float av[8] = {a1.x, a1.y, a1.z, a1.w, a2.x, a2.y, a2.z, a2.w};
            float bv[8] = {b1.x, b1.y, b1.z, b1.w, b2.x, b2.y, b2.z, b2.w};
#pragma unroll
            for (int i = 0; i < 8; i++)
#pragma unroll
                for (int j = 0; j < 8; j++) acc[i][j] += av[i] * bv[j];
        }
        __syncthreads();
    }
#pragma unroll
    for (int i = 0; i < 8; i++) {
        int r = m0 + ((i < 4) ? ty * 4 + i : 64 + ty * 4 + i - 4);
#pragma unroll
        for (int j = 0; j < 8; j++) {
            int c = n0 + ((j < 4) ? tx * 4 + j : 64 + tx * 4 + j - 4);
            g_xp[(size_t)r * 768 + c] = acc[i][j] + bi[c];
        }
    }
}

// ---------------- persistent GRU: all 512 steps, atomic-flag sync ----------------
// Inner loop uses packed fma.rn.f32x2 (SASS FFMA2): 2 fp32 MACs / instr.
#define GRU2_SMEM ((96 * 260 + 8 * 256 + 8 * 3 * 256) * 4)
__global__ __launch_bounds__(256, 1) void k_gru2(const float* __restrict__ bh) {
    extern __shared__ float sm[];
    float* ws   = sm;                          // [96][260]  Wh slice
    float* hs   = sm + 96 * 260;               // [8][256]   h_{t-1}
    float* part = sm + 96 * 260 + 8 * 256;     // [8][3][256] k-octant partials

    int tid = threadIdx.x;
    int cgx = blockIdx.x;
    int rg  = blockIdx.y;
    int cb0 = cgx << 5;
    int rb0 = rg << 3;

    for (int i = tid; i < 96 * 64; i += 256) {
        int bc = i >> 6, q = i & 63;
        int gate = bc >> 5, ch = bc & 31;
        float4 v = *(const float4*)&g_whT[(size_t)(gate * 256 + cb0 + ch) * 256 + q * 4];
        *(float4*)&ws[bc * 260 + q * 4] = v;
    }

    int uc = tid & 31;
    int kh = tid >> 5;
    int cg = cb0 + uc;
    float bhr = bh[cg], bhz = bh[256 + cg], bhn = bh[512 + cg];

    int ur = kh;
    int b  = rb0 + ur;
    const float* xpb = g_xp + (size_t)b * TT * 768;
    float* crow = g_c + (size_t)b * TT * CC;

    int sflat = tid * 8;
    int sr = sflat >> 8, skk = sflat & 255;

    const float* wr = &ws[(0  + uc) * 260 + kh * 32];
    const float* wz = &ws[(32 + uc) * 260 + kh * 32];
    const float* wn = &ws[(64 + uc) * 260 + kh * 32];

    for (int t = 0; t < TT; t++) {
        if (t == 0) {
            *(float4*)&hs[sflat]     = make_float4(0.f, 0.f, 0.f, 0.f);
            *(float4*)&hs[sflat + 4] = make_float4(0.f, 0.f, 0.f, 0.f);
        } else {
            const float4* s =
                (const float4*)&g_c[((size_t)(rb0 + sr) * TT + (t - 1)) * CC + skk];
            *(float4*)&hs[sflat]     = __ldcg(s);
            *(float4*)&hs[sflat + 4] = __ldcg(s + 1);
        }
        float xr = __ldg(&xpb[(size_t)t * 768 + cg]);
        float xz = __ldg(&xpb[(size_t)t * 768 + 256 + cg]);
        float xn = __ldg(&xpb[(size_t)t * 768 + 512 + cg]);
        __syncthreads();

        // ---- h @ Wh via packed f32x2 FMA ----
        ull p0[8], p1[8], p2[8];
#pragma unroll
        for (int r = 0; r < 8; r++) { p0[r] = 0ull; p1[r] = 0ull; p2[r] = 0ull; }
#pragma unroll
        for (int j = 0; j < 8; j++) {
            ulonglong2 W0 = *(const ulonglong2*)(wr + j * 4);
            ulonglong2 W1 = *(const ulonglong2*)(wz + j * 4);
            ulonglong2 W2 = *(const ulonglong2*)(wn + j * 4);
#pragma unroll
            for (int r = 0; r < 8; r++) {
                ulonglong2 H = *(const ulonglong2*)&hs[r * 256 + kh * 32 + j * 4];
                p0[r] = ffma2(H.x, W0.x, p0[r]);
                p0[r] = ffma2(H.y, W0.y, p0[r]);
                p1[r] = ffma2(H.x, W1.x, p1[r]);
                p1[r] = ffma2(H.y, W1.y, p1[r]);
                p2[r] = ffma2(H.x, W2.x, p2[r]);
                p2[r] = ffma2(H.y, W2.y, p2[r]);
            }
        }
#pragma unroll
        for (int r = 0; r < 8; r++) {
            part[(r * 3 + 0) * 256 + kh * 32 + uc] = pairsum(p0[r]);
            part[(r * 3 + 1) * 256 + kh * 32 + uc] = pairsum(p1[r]);
            part[(r * 3 + 2) * 256 + kh * 32 + uc] = pairsum(p2[r]);
        }
        __syncthreads();

        {
            float hr = bhr, hz = bhz, hn = bhn;
#pragma unroll
            for (int q = 0; q < 8; q++) {
                hr += part[(ur * 3 + 0) * 256 + q * 32 + uc];
                hz += part[(ur * 3 + 1) * 256 + q * 32 + uc];
                hn += part[(ur * 3 + 2) * 256 + q * 32 + uc];
            }
            float rgt = 1.f / (1.f + expf(-(xr + hr)));
            float zgt = 1.f / (1.f + expf(-(xz + hz)));
            float ngt = tanhf(xn + rgt * hn);
            float hp = hs[ur * 256 + cg];
            crow[(size_t)t * CC + cg] = (1.f - zgt) * ngt + zgt * hp;
        }

        __threadfence();
        __syncthreads();
        if (tid == 0) {
            atomicAdd(&g_sync[rg], 1u);
            unsigned target = 8u * (unsigned)(t + 1);
            unsigned v;
            do {
                asm volatile("ld.acquire.gpu.u32 %0, [%1];"
                             : "=r"(v) : "l"(&g_sync[rg]) : "memory");
            } while (v < target);
        }
        __syncthreads();
    }
}

// ---------------- fused loss: tf32 mma for both GEMM stages ----------------
// grid (500, 12), block 256 (8 warps as 2(m) x 4(n), each warp 64x32 of 128x128)
// smem: Psm[128][132] | region2{ As[128][36] + Bs[32][136]  /  Zsm[128][132] } | rnorm | red
#define LOSS_SMEM ((128 * 132 + 128 * 132 + 128 + 16) * 4)
__global__ __launch_bounds__(256) void k_loss(const float* __restrict__ Wkw,
                                              const float* __restrict__ Wkb) {
    extern __shared__ float sm[];
    float* Psm = sm;                     // [128][132]
    float* As  = sm + 128 * 132;         // [128][36]  (stage1: c_t rows, tf32)
    float* Bs  = As + 128 * 36;          // [32][136]  (stage1: Wk k-chunk, tf32)
    float* Zsm = sm + 128 * 132;         // [128][132] (stage2, aliases As/Bs)
    float* rnorm = sm + 2 * 128 * 132;
    float* red = rnorm + 128;

    int t = blockIdx.x, k = blockIdx.y;
    int tid = threadIdx.x;
    int lane = tid & 31, wid = tid >> 5;
    int g = lane >> 2, tq = lane & 3;
    int R0 = (wid >> 2) * 64;            // warp's row base (0 or 64)
    int C0 = (wid & 3) * 32;             // warp's col base (0/32/64/96)

    // ======== stage 1: P = c_t @ Wk[k]  (128x128, K=256), tf32 mma ========
    float acc[4][4][4];
#pragma unroll
    for (int mt = 0; mt < 4; mt++)
#pragma unroll
        for (int nt = 0; nt < 4; nt++)
#pragma unroll
            for (int i = 0; i < 4; i++) acc[mt][nt][i] = 0.f;

    for (int kc = 0; kc < CC; kc += 32) {
        for (int i = tid; i < 4096; i += 256) {      // A: [r][kk], pitch 36
            int r = i >> 5, kk = i & 31;
            As[r * 36 + kk] =
                __uint_as_float(f2tf(g_c[((size_t)r * TT + t) * CC + kc + kk]));
        }
        for (int i = tid; i < 4096; i += 256) {      // B: [kk][d], pitch 136
            int kk = i >> 7, d = i & 127;
            Bs[kk * 136 + d] =
                __uint_as_float(f2tf(Wkw[((size_t)k * CC + kc + kk) * DD + d]));
        }
        __syncthreads();
#pragma unroll
        for (int ks = 0; ks < 4; ks++) {
            int k0 = ks * 8;
            uint af[4][4];
#pragma unroll
            for (int mt = 0; mt < 4; mt++) {
                int r = R0 + mt * 16 + g;
                af[mt][0] = __float_as_uint(As[r * 36 + k0 + tq]);
                af[mt][1] = __float_as_uint(As[(r + 8) * 36 + k0 + tq]);
                af[mt][2] = __float_as_uint(As[r * 36 + k0 + tq + 4]);
                af[mt][3] = __float_as_uint(As[(r + 8) * 36 + k0 + tq + 4]);
            }
            uint bf[4][2];
#pragma unroll
            for (int nt = 0; nt < 4; nt++) {
                int c = C0 + nt * 8 + g;
                bf[nt][0] = __float_as_uint(Bs[(k0 + tq) * 136 + c]);
                bf[nt][1] = __float_as_uint(Bs[(k0 + tq + 4) * 136 + c]);
            }
#pragma unroll
            for (int mt = 0; mt < 4; mt++)
#pragma unroll
                for (int nt = 0; nt < 4; nt++) MMA_TF32(acc[mt][nt], af[mt], bf[nt]);
        }
        __syncthreads();
    }

    // epilogue: +bias, round to tf32, stash in Psm (stage2 A-operand)
#pragma unroll
    for (int nt = 0; nt < 4; nt++) {
        int c0 = C0 + nt * 8 + 2 * tq;
        float bia0 = __ldg(&Wkb[k * DD + c0]);
        float bia1 = __ldg(&Wkb[k * DD + c0 + 1]);
#pragma unroll
        for (int mt = 0; mt < 4; mt++) {
            int r = R0 + mt * 16 + g;
            Psm[r * 132 + c0]           = __uint_as_float(f2tf(acc[mt][nt][0] + bia0));
            Psm[r * 132 + c0 + 1]       = __uint_as_float(f2tf(acc[mt][nt][1] + bia1));
            Psm[(r + 8) * 132 + c0]     = __uint_as_float(f2tf(acc[mt][nt][2] + bia0));
            Psm[(r + 8) * 132 + c0 + 1] = __uint_as_float(f2tf(acc[mt][nt][3] + bia1));
        }
    }
    __syncthreads();

    // load zf tile (tf32-rounded): Z[c][d] = z[c, t+k+1, d]
    for (int i = tid; i < 16384; i += 256) {
        int cidx = i >> 7, d = i & 127;
        Zsm[cidx * 132 + d] =
            __uint_as_float(f2tf(g_z[((size_t)cidx * TT + t + k + 1) * DD + d]));
    }
    // per-row 1/||P||  (from the same tf32 values the mma consumes)
    if (tid < 128) {
        const float4* p = (const float4*)&Psm[tid * 132];
        float ss = 0.f;
#pragma unroll
        for (int q = 0; q < 32; q++) {
            float4 v = p[q];
            ss += v.x * v.x + v.y * v.y + v.z * v.z + v.w * v.w;
        }
        rnorm[tid] = 1.f / fmaxf(sqrtf(ss), 1e-12f);
    }
    __syncthreads();

    // ======== stage 2: S = P @ Z^T  (128x128, K=128), tf32 mma ========
    float acc2[4][4][4];
#pragma unroll
    for (int mt = 0; mt < 4; mt++)
#pragma unroll
        for (int nt = 0; nt < 4; nt++)
#pragma unroll
            for (int i = 0; i < 4; i++) acc2[mt][nt][i] = 0.f;

#pragma unroll
    for (int ks = 0; ks < 16; ks++) {
        int k0 = ks * 8;
        uint af[4][4];
#pragma unroll
        for (int mt = 0; mt < 4; mt++) {
            int r = R0 + mt * 16 + g;
            af[mt][0] = __float_as_uint(Psm[r * 132 + k0 + tq]);
            af[mt][1] = __float_as_uint(Psm[(r + 8) * 132 + k0 + tq]);
            af[mt][2] = __float_as_uint(Psm[r * 132 + k0 + tq + 4]);
            af[mt][3] = __float_as_uint(Psm[(r + 8) * 132 + k0 + tq + 4]);
        }
        uint bf[4][2];
#pragma unroll
        for (int nt = 0; nt < 4; nt++) {
            int c = C0 + nt * 8 + g;
            bf[nt][0] = __float_as_uint(Zsm[c * 132 + k0 + tq]);
            bf[nt][1] = __float_as_uint(Zsm[c * 132 + k0 + tq + 4]);
        }
#pragma unroll
        for (int mt = 0; mt < 4; mt++)
#pragma unroll
            for (int nt = 0; nt < 4; nt++) MMA_TF32(acc2[mt][nt], af[mt], bf[nt]);
    }
    __syncthreads();   // all Psm reads done before logits overwrite

    // logits = rnorm[b] * S / TEMP  -> Psm (fp32)
#pragma unroll
    for (int mt = 0; mt < 4; mt++) {
        int r = R0 + mt * 16 + g;
        float rn0 = rnorm[r] * 10.0f;
        float rn1 = rnorm[r + 8] * 10.0f;
#pragma unroll
        for (int nt = 0; nt < 4; nt++) {
            int c0 = C0 + nt * 8 + 2 * tq;
            Psm[r * 132 + c0]           = acc2[mt][nt][0] * rn0;
            Psm[r * 132 + c0 + 1]       = acc2[mt][nt][1] * rn0;
            Psm[(r + 8) * 132 + c0]     = acc2[mt][nt][2] * rn1;
            Psm[(r + 8) * 132 + c0 + 1] = acc2[mt][nt][3] * rn1;
        }
    }
    __syncthreads();

    // per-row LSE, diag, argmax
    float lossv = 0.f;
    int corr = 0;
    if (tid < 128) {
        const float* L = &Psm[tid * 132];
        float m = -1e30f;
        int am = 0;
        for (int cc = 0; cc < 128; cc++) {
            float v = L[cc];
            if (v > m) { m = v; am = cc; }
        }
        float s = 0.f;
        for (int cc = 0; cc < 128; cc++) s += expf(L[cc] - m);
        lossv = m + logf(s) - L[tid];
        corr = (am == tid) ? 1 : 0;
    }
#pragma unroll
    for (int o = 16; o; o >>= 1) {
        lossv += __shfl_xor_sync(0xffffffffu, lossv, o);
        corr += __shfl_xor_sync(0xffffffffu, corr, o);
    }
    if ((tid & 31) == 0) {
        red[wid] = lossv;
        ((int*)red)[8 + wid] = corr;
    }
    __syncthreads();
    if (tid == 0) {
        float s = 0.f;
        int ct = 0;
        for (int w = 0; w < 8; w++) { s += red[w]; ct += ((int*)red)[8 + w]; }
        atomicAdd(&g_loss, (double)s);
        atomicAdd(&g_cnt, ct);
    }
}

// ---------------- finalize scalars ----------------
__global__ void k_fin(float* out) {
    const double n = (double)KS * TP * BB;
    out[0] = (float)(g_loss / n);
    out[1] = (float)(100.0 * (double)g_cnt / n);
}

// ---------------- copy z_seq, c_seq into d_out ----------------
__global__ void k_copy(float* out, long long out_size) {
    size_t i0 = (size_t)blockIdx.x * blockDim.x + threadIdx.x;
    size_t stride = (size_t)gridDim.x * blockDim.x;
    const size_t NZ = (size_t)BB * TT * DD;
    const size_t NC = (size_t)BB * TT * CC;
    size_t avail = (out_size > 2) ? (size_t)(out_size - 2) : 0;
    size_t nz = NZ < avail ? NZ : avail;
    size_t nc2 = (avail > NZ) ? ((NC < avail - NZ) ? NC : avail - NZ) : 0;
    float2* oz = (float2*)(out + 2);
    const float2* z2 = (const float2*)g_z;
    for (size_t i = i0; i < nz / 2; i += stride) oz[i] = z2[i];
    float2* oc = (float2*)(out + 2 + NZ);
    const float2* c2 = (const float2*)g_c;
    for (size_t i = i0; i < nc2 / 2; i += stride) oc[i] = c2[i];
}

extern "C" void kernel_launch(void* const* d_in, const int* in_sizes, int n_in,
                              void* d_out, int out_size) {
    const float* rr  = (const float*)d_in[0];
    const float* We  = (const float*)d_in[1];
    const float* be  = (const float*)d_in[2];
    const float* Wi  = (const float*)d_in[3];
    const float* Wh  = (const float*)d_in[4];
    const float* bi  = (const float*)d_in[5];
    const float* bh  = (const float*)d_in[6];
    const float* Wkw = (const float*)d_in[7];
    const float* Wkb = (const float*)d_in[8];
    float* out = (float*)d_out;

    cudaFuncSetAttribute(k_gru2, cudaFuncAttributeMaxDynamicSharedMemorySize, GRU2_SMEM);
    cudaFuncSetAttribute(k_loss, cudaFuncAttributeMaxDynamicSharedMemorySize, LOSS_SMEM);

    k_init<<<1, 1>>>();
    k_z<<<dim3(TT / 64, BB), 128>>>(rr, We, be);
    k_wht<<<(3 * CC * CC + 255) / 256, 256>>>(Wh);
    k_xproj<<<dim3(6, (BB * TT) / 128), 256>>>(Wi, bi);
    k_gru2<<<dim3(8, 16), 256, GRU2_SMEM>>>(bh);
    k_loss<<<dim3(TP, KS), 256, LOSS_SMEM>>>(Wkw, Wkb);
    k_fin<<<1, 1>>>(out);
    k_copy<<<2048, 256>>>(out, (long long)out_size);
}

// round 11
// speedup vs baseline: 11.2178x; 1.1659x over previous
#include <cuda_runtime.h>
#include <math.h>

#define BB 128
#define TT 512
#define WW 64
#define DD 128
#define CC 256
#define KS 12
#define TP 500

typedef unsigned long long ull;
typedef unsigned int uint;

// ---------------- device scratch (no runtime allocation allowed) ----------------
__device__ float g_z[(size_t)BB * TT * DD];        // 33.5 MB  (B,T,D) normalized z
__device__ float g_xp[(size_t)BB * TT * 3 * CC];   // 201 MB   (B,T,768) x_proj
__device__ float g_c[(size_t)BB * TT * CC];        // 67 MB    (B,T,C) GRU hidden states
__device__ float g_whT[3 * CC * CC];               // Wh transposed: [col][k]
__device__ double g_loss;
__device__ int    g_cnt;
__device__ unsigned g_sync[16];                    // per-rowgroup step counters

__device__ __forceinline__ uint f2tf(float f) {
    uint u;
    asm("cvt.rna.tf32.f32 %0, %1;" : "=r"(u) : "f"(f));
    return u;
}
__device__ __forceinline__ ull ffma2(ull a, ull b, ull c) {
    ull d;
    asm("fma.rn.f32x2 %0, %1, %2, %3;" : "=l"(d) : "l"(a), "l"(b), "l"(c));
    return d;
}
__device__ __forceinline__ float pairsum(ull v) {
    float lo, hi;
    asm("mov.b64 {%0, %1}, %2;" : "=f"(lo), "=f"(hi) : "l"(v));
    return lo + hi;
}
#define MMA_TF32(d, a, b) \
    asm volatile("mma.sync.aligned.m16n8k8.row.col.f32.tf32.tf32.f32 " \
                 "{%0,%1,%2,%3},{%4,%5,%6,%7},{%8,%9},{%0,%1,%2,%3};" \
                 : "+f"((d)[0]), "+f"((d)[1]), "+f"((d)[2]), "+f"((d)[3]) \
                 : "r"((a)[0]), "r"((a)[1]), "r"((a)[2]), "r"((a)[3]), \
                   "r"((b)[0]), "r"((b)[1]))

// ---------------- init accumulators ----------------
__global__ void k_init() {
    g_loss = 0.0; g_cnt = 0;
    for (int i = 0; i < 16; i++) g_sync[i] = 0u;
}

// ---------------- transpose Wh once per launch ----------------
__global__ void k_wht(const float* __restrict__ Wh) {
    int i = blockIdx.x * 256 + threadIdx.x;
    if (i < 3 * CC * CC) {
        int kk = i & 255;
        int col = i >> 8;
        g_whT[i] = Wh[(size_t)kk * 768 + col];
    }
}

// ---------------- z = l2norm(rr @ We + be) ----------------
__global__ __launch_bounds__(128) void k_z(const float* __restrict__ rr,
                                           const float* __restrict__ We,
                                           const float* __restrict__ be) {
    __shared__ float Wes[64 * 128];
    __shared__ float rs[64];
    __shared__ float red[4];
    int b = blockIdx.y;
    int t0 = blockIdx.x << 6;
    int tid = threadIdx.x;
    for (int i = tid; i < 64 * 128; i += 128) Wes[i] = We[i];
    float bias = be[tid];
    __syncthreads();
    for (int tt = 0; tt < 64; tt++) {
        int t = t0 + tt;
        if (tid < 64) rs[tid] = rr[((size_t)b * TT + t) * WW + tid];
        __syncthreads();
        float acc = bias;
#pragma unroll
        for (int w = 0; w < 64; w++) acc += rs[w] * Wes[w * 128 + tid];
        float ss = acc * acc;
#pragma unroll
        for (int o = 16; o; o >>= 1) ss += __shfl_xor_sync(0xffffffffu, ss, o);
        if ((tid & 31) == 0) red[tid >> 5] = ss;
        __syncthreads();
        float tot = red[0] + red[1] + red[2] + red[3];
        float scale = 1.0f / fmaxf(sqrtf(tot), 1e-12f);
        g_z[((size_t)b * TT + t) * DD + tid] = acc * scale;
        __syncthreads();
    }
}

// ---------------- x_proj = z @ Wi + bi  (M=65536, N=768, K=128) ----------------
__global__ __launch_bounds__(256) void k_xproj(const float* __restrict__ Wi,
                                               const float* __restrict__ bi) {
    __shared__ float As[32 * 132];
    __shared__ float Bs[32 * 132];
    int tid = threadIdx.x;
    int tx = tid & 15, ty = tid >> 4;
    int m0 = blockIdx.y << 7, n0 = blockIdx.x << 7;
    float acc[8][8] = {};
    for (int kc = 0; kc < DD; kc += 32) {
        for (int i = tid; i < 4096; i += 256) {
            int r = i >> 5, kk = i & 31;
            As[kk * 132 + r] = g_z[(size_t)(m0 + r) * DD + kc + kk];
        }
        for (int i = tid; i < 4096; i += 256) {
            int kk = i >> 7, n = i & 127;
            Bs[kk * 132 + n] = Wi[(size_t)(kc + kk) * 768 + n0 + n];
        }
        __syncthreads();
#pragma unroll
        for (int kk = 0; kk < 32; kk++) {
            float4 a1 = *(const float4*)&As[kk * 132 + ty * 4];
            float4 a2 = *(const float4*)&As[kk * 132 + 64 + ty * 4];
            float4 b1 = *(const float4*)&Bs[kk * 132 + tx * 4];
            float4 b2 = *(const float4*)&Bs[kk * 132 + 64 + tx * 4];
            float av[8] = {a1.x, a1.y, a1.z, a1.w, a2.x, a2.y, a2.z, a2.w};
            float bv[8] = {b1.x, b1.y, b1.z, b1.w, b2.x, b2.y, b2.z, b2.w};
#pragma unroll
            for (int i = 0; i < 8; i++)
#pragma unroll
                for (int j = 0; j < 8; j++) acc[i][j] += av[i] * bv[j];
        }
        __syncthreads();
    }
#pragma unroll
    for (int i = 0; i < 8; i++) {
        int r = m0 + ((i < 4) ? ty * 4 + i : 64 + ty * 4 + i - 4);
#pragma unroll
        for (int j = 0; j < 8; j++) {
            int c = n0 + ((j < 4) ? tx * 4 + j : 64 + tx * 4 + j - 4);
            g_xp[(size_t)r * 768 + c] = acc[i][j] + bi[c];
        }
    }
}

// ---------------- persistent GRU: all 512 steps, atomic-flag sync ----------------
// Wh in smem with XOR swizzle. FIX vs R10: H is read at LOGICAL chunk j
// (kofs = kh*32 + j*4) while W reads de-swizzle physical slot (j^s7) back to
// logical j — so H/W pairing is correct and accumulation order is bit-exact
// with the R9 pass. W reads hit 8 distinct bank-groups across lanes -> 4-phase
// conflict-free LDS.128; H reads are warp-broadcast.
#define GRU2_SMEM ((96 * 256 + 8 * 256 + 8 * 3 * 256) * 4)
__global__ __launch_bounds__(256, 1) void k_gru2(const float* __restrict__ bh) {
    extern __shared__ float sm[];
    float* ws   = sm;                          // [96 cols][64 float4], XOR-swizzled
    float* hs   = sm + 96 * 256;               // [8][256]   h_{t-1}
    float* part = sm + 96 * 256 + 8 * 256;     // [8][3][256] k-octant partials

    int tid = threadIdx.x;
    int cgx = blockIdx.x;
    int rg  = blockIdx.y;
    int cb0 = cgx << 5;
    int rb0 = rg << 3;

    // ---- load Wh slice once, swizzled: slot = col*64 + (kgrp ^ (col&7)) ----
    for (int i = tid; i < 96 * 64; i += 256) {
        int bc = i >> 6, kgrp = i & 63;
        int gate = bc >> 5, ch = bc & 31;
        float4 v = *(const float4*)&g_whT[(size_t)(gate * 256 + cb0 + ch) * 256 + kgrp * 4];
        *(float4*)&ws[(bc * 64 + (kgrp ^ (bc & 7))) * 4] = v;
    }

    int uc = tid & 31;
    int kh = tid >> 5;
    int cg = cb0 + uc;
    float bhr = bh[cg], bhz = bh[256 + cg], bhn = bh[512 + cg];

    int ur = kh;
    int b  = rb0 + ur;
    const float* xpb = g_xp + (size_t)b * TT * 768;
    float* crow = g_c + (size_t)b * TT * CC;

    int sflat = tid * 8;
    int sr = sflat >> 8, skk = sflat & 255;

    const ulonglong2* ws4 = (const ulonglong2*)ws;
    int s7 = uc & 7;
    int wb0 = (0  + uc) * 64 + kh * 8;
    int wb1 = (32 + uc) * 64 + kh * 8;
    int wb2 = (64 + uc) * 64 + kh * 8;

    for (int t = 0; t < TT; t++) {
        if (t == 0) {
            *(float4*)&hs[sflat]     = make_float4(0.f, 0.f, 0.f, 0.f);
            *(float4*)&hs[sflat + 4] = make_float4(0.f, 0.f, 0.f, 0.f);
        } else {
            const float4* s =
                (const float4*)&g_c[((size_t)(rb0 + sr) * TT + (t - 1)) * CC + skk];
            *(float4*)&hs[sflat]     = __ldcg(s);
            *(float4*)&hs[sflat + 4] = __ldcg(s + 1);
        }
        float xr = __ldg(&xpb[(size_t)t * 768 + cg]);
        float xz = __ldg(&xpb[(size_t)t * 768 + 256 + cg]);
        float xn = __ldg(&xpb[(size_t)t * 768 + 512 + cg]);
        __syncthreads();

        // ---- h @ Wh via packed f32x2 FMA; W de-swizzled to logical j ----
        ull p0[8], p1[8], p2[8];
#pragma unroll
        for (int r = 0; r < 8; r++) { p0[r] = 0ull; p1[r] = 0ull; p2[r] = 0ull; }
#pragma unroll
        for (int j = 0; j < 8; j++) {
            int js = j ^ s7;                   // physical slot within kh-block
            ulonglong2 W0 = ws4[wb0 + js];     // logical k-chunk j
            ulonglong2 W1 = ws4[wb1 + js];
            ulonglong2 W2 = ws4[wb2 + js];
            int kofs = kh * 32 + j * 4;        // logical k-chunk j (FIX)
#pragma unroll
            for (int r = 0; r < 8; r++) {
                ulonglong2 H = *(const ulonglong2*)&hs[r * 256 + kofs];
                p0[r] = ffma2(H.x, W0.x, p0[r]);
                p0[r] = ffma2(H.y, W0.y, p0[r]);
                p1[r] = ffma2(H.x, W1.x, p1[r]);
                p1[r] = ffma2(H.y, W1.y, p1[r]);
                p2[r] = ffma2(H.x, W2.x, p2[r]);
                p2[r] = ffma2(H.y, W2.y, p2[r]);
            }
        }
#pragma unroll
        for (int r = 0; r < 8; r++) {
            part[(r * 3 + 0) * 256 + kh * 32 + uc] = pairsum(p0[r]);
            part[(r * 3 + 1) * 256 + kh * 32 + uc] = pairsum(p1[r]);
            part[(r * 3 + 2) * 256 + kh * 32 + uc] = pairsum(p2[r]);
        }
        __syncthreads();

        {
            float hr = bhr, hz = bhz, hn = bhn;
#pragma unroll
            for (int q = 0; q < 8; q++) {
                hr += part[(ur * 3 + 0) * 256 + q * 32 + uc];
                hz += part[(ur * 3 + 1) * 256 + q * 32 + uc];
                hn += part[(ur * 3 + 2) * 256 + q * 32 + uc];
            }
            float rgt = 1.f / (1.f + expf(-(xr + hr)));
            float zgt = 1.f / (1.f + expf(-(xz + hz)));
            float ngt = tanhf(xn + rgt * hn);
            float hp = hs[ur * 256 + cg];
            crow[(size_t)t * CC + cg] = (1.f - zgt) * ngt + zgt * hp;
        }

        // ---- release h_t (CG grid-sync pattern: bar + 1-thread red.release) ----
        __syncthreads();
        if (tid == 0) {
            asm volatile("red.release.gpu.global.add.u32 [%0], %1;"
                         :: "l"(&g_sync[rg]), "r"(1u) : "memory");
            unsigned target = 8u * (unsigned)(t + 1);
            unsigned v;
            do {
                asm volatile("ld.acquire.gpu.u32 %0, [%1];"
                             : "=r"(v) : "l"(&g_sync[rg]) : "memory");
            } while (v < target);
        }
        __syncthreads();
    }
}

// ---------------- fused loss: tf32 mma, 512 threads (16 warps, 4x4 grid) ----------------
#define LOSS_SMEM ((128 * 132 + 128 * 132 + 128 + 64) * 4)
__global__ __launch_bounds__(512) void k_loss(const float* __restrict__ Wkw,
                                              const float* __restrict__ Wkb) {
    extern __shared__ float sm[];
    float* Psm = sm;                     // [128][132]
    float* As  = sm + 128 * 132;         // [128][36]  (stage1 A, tf32)
    float* Bs  = As + 128 * 36;          // [32][136]  (stage1 B, tf32)
    float* Zsm = sm + 128 * 132;         // [128][132] (stage2, aliases As/Bs)
    float* rnorm = sm + 2 * 128 * 132;
    float* red = rnorm + 128;            // 16 floats + 16 ints

    int t = blockIdx.x, k = blockIdx.y;
    int tid = threadIdx.x;
    int lane = tid & 31, wid = tid >> 5;
    int g = lane >> 2, tq = lane & 3;
    int R0 = (wid >> 2) * 32;
    int C0 = (wid & 3) * 32;

    // ======== stage 1: P = c_t @ Wk[k]  (128x128, K=256), tf32 mma ========
    float acc[2][4][4];
#pragma unroll
    for (int mt = 0; mt < 2; mt++)
#pragma unroll
        for (int nt = 0; nt < 4; nt++)
#pragma unroll
            for (int i = 0; i < 4; i++) acc[mt][nt][i] = 0.f;

    for (int kc = 0; kc < CC; kc += 32) {
        for (int i = tid; i < 4096; i += 512) {
            int r = i >> 5, kk = i & 31;
            As[r * 36 + kk] =
                __uint_as_float(f2tf(g_c[((size_t)r * TT + t) * CC + kc + kk]));
        }
        for (int i = tid; i < 4096; i += 512) {
            int kk = i >> 7, d = i & 127;
            Bs[kk * 136 + d] =
                __uint_as_float(f2tf(Wkw[((size_t)k * CC + kc + kk) * DD + d]));
        }
        __syncthreads();
#pragma unroll
        for (int ks = 0; ks < 4; ks++) {
            int k0 = ks * 8;
            uint af[2][4];
#pragma unroll
            for (int mt = 0; mt < 2; mt++) {
                int r = R0 + mt * 16 + g;
                af[mt][0] = __float_as_uint(As[r * 36 + k0 + tq]);
                af[mt][1] = __float_as_uint(As[(r + 8) * 36 + k0 + tq]);
                af[mt][2] = __float_as_uint(As[r * 36 + k0 + tq + 4]);
                af[mt][3] = __float_as_uint(As[(r + 8) * 36 + k0 + tq + 4]);
            }
            uint bf[4][2];
#pragma unroll
            for (int nt = 0; nt < 4; nt++) {
                int c = C0 + nt * 8 + g;
                bf[nt][0] = __float_as_uint(Bs[(k0 + tq) * 136 + c]);
                bf[nt][1] = __float_as_uint(Bs[(k0 + tq + 4) * 136 + c]);
            }
#pragma unroll
            for (int mt = 0; mt < 2; mt++)
#pragma unroll
                for (int nt = 0; nt < 4; nt++) MMA_TF32(acc[mt][nt], af[mt], bf[nt]);
        }
        __syncthreads();
    }

    // epilogue: +bias, round to tf32, stash in Psm (stage2 A-operand)
#pragma unroll
    for (int nt = 0; nt < 4; nt++) {
        int c0 = C0 + nt * 8 + 2 * tq;
        float bia0 = __ldg(&Wkb[k * DD + c0]);
        float bia1 = __ldg(&Wkb[k * DD + c0 + 1]);
#pragma unroll
        for (int mt = 0; mt < 2; mt++) {
            int r = R0 + mt * 16 + g;
            Psm[r * 132 + c0]           = __uint_as_float(f2tf(acc[mt][nt][0] + bia0));
            Psm[r * 132 + c0 + 1]       = __uint_as_float(f2tf(acc[mt][nt][1] + bia1));
            Psm[(r + 8) * 132 + c0]     = __uint_as_float(f2tf(acc[mt][nt][2] + bia0));
            Psm[(r + 8) * 132 + c0 + 1] = __uint_as_float(f2tf(acc[mt][nt][3] + bia1));
        }
    }
    __syncthreads();

    // load zf tile (tf32-rounded): Z[c][d] = z[c, t+k+1, d]
    for (int i = tid; i < 16384; i += 512) {
        int cidx = i >> 7, d = i & 127;
        Zsm[cidx * 132 + d] =
            __uint_as_float(f2tf(g_z[((size_t)cidx * TT + t + k + 1) * DD + d]));
    }
    // per-row 1/||P||
    if (tid < 128) {
        const float4* p = (const float4*)&Psm[tid * 132];
        float ss = 0.f;
#pragma unroll
        for (int q = 0; q < 32; q++) {
            float4 v = p[q];
            ss += v.x * v.x + v.y * v.y + v.z * v.z + v.w * v.w;
        }
        rnorm[tid] = 1.f / fmaxf(sqrtf(ss), 1e-12f);
    }
    __syncthreads();

    // ======== stage 2: S = P @ Z^T  (128x128, K=128), tf32 mma ========
    float acc2[2][4][4];
#pragma unroll
    for (int mt = 0; mt < 2; mt++)
#pragma unroll
        for (int nt = 0; nt < 4; nt++)
#pragma unroll
            for (int i = 0; i < 4; i++) acc2[mt][nt][i] = 0.f;

#pragma unroll
    for (int ks = 0; ks < 16; ks++) {
        int k0 = ks * 8;
        uint af[2][4];
#pragma unroll
        for (int mt = 0; mt < 2; mt++) {
            int r = R0 + mt * 16 + g;
            af[mt][0] = __float_as_uint(Psm[r * 132 + k0 + tq]);
            af[mt][1] = __float_as_uint(Psm[(r + 8) * 132 + k0 + tq]);
            af[mt][2] = __float_as_uint(Psm[r * 132 + k0 + tq + 4]);
            af[mt][3] = __float_as_uint(Psm[(r + 8) * 132 + k0 + tq + 4]);
        }
        uint bf[4][2];
#pragma unroll
        for (int nt = 0; nt < 4; nt++) {
            int c = C0 + nt * 8 + g;
            bf[nt][0] = __float_as_uint(Zsm[c * 132 + k0 + tq]);
            bf[nt][1] = __float_as_uint(Zsm[c * 132 + k0 + tq + 4]);
        }
#pragma unroll
        for (int mt = 0; mt < 2; mt++)
#pragma unroll
            for (int nt = 0; nt < 4; nt++) MMA_TF32(acc2[mt][nt], af[mt], bf[nt]);
    }
    __syncthreads();   // all Psm reads done before logits overwrite

    // logits = rnorm[b] * S / TEMP  -> Psm (fp32)
#pragma unroll
    for (int mt = 0; mt < 2; mt++) {
        int r = R0 + mt * 16 + g;
        float rn0 = rnorm[r] * 10.0f;
        float rn1 = rnorm[r + 8] * 10.0f;
#pragma unroll
        for (int nt = 0; nt < 4; nt++) {
            int c0 = C0 + nt * 8 + 2 * tq;
            Psm[r * 132 + c0]           = acc2[mt][nt][0] * rn0;
            Psm[r * 132 + c0 + 1]       = acc2[mt][nt][1] * rn0;
            Psm[(r + 8) * 132 + c0]     = acc2[mt][nt][2] * rn1;
            Psm[(r + 8) * 132 + c0 + 1] = acc2[mt][nt][3] * rn1;
        }
    }
    __syncthreads();

    // per-row LSE, diag, argmax: 4 lanes per row
    float lossv = 0.f;
    int corr = 0;
    {
        int row = tid >> 2, sub = tid & 3;
        const float* L = &Psm[row * 132];
        int c0 = sub * 32;
        float m = -1e30f;
        int am = 0;
        for (int cc = c0; cc < c0 + 32; cc++) {
            float v = L[cc];
            if (v > m) { m = v; am = cc; }
        }
#pragma unroll
        for (int o = 1; o <= 2; o <<= 1) {
            float om = __shfl_xor_sync(0xffffffffu, m, o);
            int oa = __shfl_xor_sync(0xffffffffu, am, o);
            if (om > m || (om == m && oa < am)) { m = om; am = oa; }
        }
        float s = 0.f;
        for (int cc = c0; cc < c0 + 32; cc++) s += expf(L[cc] - m);
#pragma unroll
        for (int o = 1; o <= 2; o <<= 1) s += __shfl_xor_sync(0xffffffffu, s, o);
        if (sub == 0) {
            lossv = m + logf(s) - L[row];
            corr = (am == row) ? 1 : 0;
        }
    }
#pragma unroll
    for (int o = 16; o; o >>= 1) {
        lossv += __shfl_xor_sync(0xffffffffu, lossv, o);
        corr += __shfl_xor_sync(0xffffffffu, corr, o);
    }
    if (lane == 0) {
        red[wid] = lossv;
        ((int*)red)[16 + wid] = corr;
    }
    __syncthreads();
    if (tid == 0) {
        float s = 0.f;
        int ct = 0;
        for (int w = 0; w < 16; w++) { s += red[w]; ct += ((int*)red)[16 + w]; }
        atomicAdd(&g_loss, (double)s);
        atomicAdd(&g_cnt, ct);
    }
}

// ---------------- finalize scalars ----------------
__global__ void k_fin(float* out) {
    const double n = (double)KS * TP * BB;
    out[0] = (float)(g_loss / n);
    out[1] = (float)(100.0 * (double)g_cnt / n);
}

// ---------------- copy z_seq, c_seq into d_out ----------------
__global__ void k_copy(float* out, long long out_size) {
    size_t i0 = (size_t)blockIdx.x * blockDim.x + threadIdx.x;
    size_t stride = (size_t)gridDim.x * blockDim.x;
    const size_t NZ = (size_t)BB * TT * DD;
    const size_t NC = (size_t)BB * TT * CC;
    size_t avail = (out_size > 2) ? (size_t)(out_size - 2) : 0;
    size_t nz = NZ < avail ? NZ : avail;
    size_t nc2 = (avail > NZ) ? ((NC < avail - NZ) ? NC : avail - NZ) : 0;
    float2* oz = (float2*)(out + 2);
    const float2* z2 = (const float2*)g_z;
    for (size_t i = i0; i < nz / 2; i += stride) oz[i] = z2[i];
    float2* oc = (float2*)(out + 2 + NZ);
    const float2* c2 = (const float2*)g_c;
    for (size_t i = i0; i < nc2 / 2; i += stride) oc[i] = c2[i];
}

extern "C" void kernel_launch(void* const* d_in, const int* in_sizes, int n_in,
                              void* d_out, int out_size) {
    const float* rr  = (const float*)d_in[0];
    const float* We  = (const float*)d_in[1];
    const float* be  = (const float*)d_in[2];
    const float* Wi  = (const float*)d_in[3];
    const float* Wh  = (const float*)d_in[4];
    const float* bi  = (const float*)d_in[5];
    const float* bh  = (const float*)d_in[6];
    const float* Wkw = (const float*)d_in[7];
    const float* Wkb = (const float*)d_in[8];
    float* out = (float*)d_out;

    cudaFuncSetAttribute(k_gru2, cudaFuncAttributeMaxDynamicSharedMemorySize, GRU2_SMEM);
    cudaFuncSetAttribute(k_loss, cudaFuncAttributeMaxDynamicSharedMemorySize, LOSS_SMEM);

    k_init<<<1, 1>>>();
    k_z<<<dim3(TT / 64, BB), 128>>>(rr, We, be);
    k_wht<<<(3 * CC * CC + 255) / 256, 256>>>(Wh);
    k_xproj<<<dim3(6, (BB * TT) / 128), 256>>>(Wi, bi);
    k_gru2<<<dim3(8, 16), 256, GRU2_SMEM>>>(bh);
    k_loss<<<dim3(TP, KS), 512, LOSS_SMEM>>>(Wkw, Wkb);
    k_fin<<<1, 1>>>(out);
    k_copy<<<2048, 256>>>(out, (long long)out_size);
}